// round 17
// baseline (speedup 1.0000x reference)
#include <cuda_runtime.h>
#include <math.h>

#define BB   128            // batch
#define TT   512            // time steps
#define HH   256            // hidden
#define XX   64             // feature / output
#define G3   768            // 3*H
#define HB   (HH * BB)      // 32768 cells per map

// ---------------- device scratch (static: no runtime allocation) ----------------
__device__ float g_hid[(size_t)(TT + 1) * HB];  // hidden_t at slot t   [t][h][b]
__device__ float g_hbB[(size_t)(TT + 2) * HB];  // B_s at slot s (gi_s input) [s][h][b]
__device__ float g_Wc [G3 * HH];                // W_ih @ W_out   [768][256]
__device__ float g_WoT[HH * XX];                // W_out transposed [h][x]
__device__ float g_bc [G3];                     // b_ih + W_ih @ b_out
__device__ float g_m0f[TT], g_m1f[TT];
__device__ int   g_gidx[TT], g_pidx[TT];        // -1 => zero placeholder
__device__ unsigned g_ctr[8 * 64];              // per-group split counters: [bg*64]=low, [bg*64+16]=high

typedef unsigned long long ull;

// ---------------- packed f32x2 ops (Blackwell) ----------------
#define FMA2(d, a, b) asm("fma.rn.f32x2 %0, %1, %2, %3;" \
                          : "=l"(d) : "l"(a), "l"(b), "l"(d))
#define ADD2(d, a, b) asm("add.rn.f32x2 %0, %1, %2;" \
                          : "=l"(d) : "l"(a), "l"(b))
#define DUP2(d, a) asm("mov.b64 %0, {%1, %1};" : "=l"(d) : "f"(a))
__device__ __forceinline__ float lo32(ull v) {
    return __uint_as_float((unsigned)(v & 0xffffffffull));
}
__device__ __forceinline__ float hi32(ull v) {
    return __uint_as_float((unsigned)(v >> 32));
}

#define CP_ASYNC16(smem_u32, gptr) \
    asm volatile("cp.async.cg.shared.global [%0], [%1], 16;" \
                 :: "r"(smem_u32), "l"(gptr) : "memory")
#define CP_COMMIT()   asm volatile("cp.async.commit_group;" ::: "memory")
#define CP_WAIT(n)    asm volatile("cp.async.wait_group %0;" :: "n"(n) : "memory")

// ---------------- shared GEMM helpers ----------------
// acc[bb][g] packs (h0,h1). aBase pre-offset by bq*4; wBase pre-offset by slot.
__device__ __forceinline__ void gemm_pass(const float* aBase, const float* wBase,
                                          int kq, int j0, int j1, ull acc[4][3])
{
    #pragma unroll
    for (int j = j0; j < j1; j++) {
        int k = kq + 8 * j;
        float4 av = *(const float4*)(aBase + (size_t)k * 20);
        const float* w = wBase + (size_t)k * 128;
        ulonglong2 wrz = *(const ulonglong2*)w;
        ull wn = *(const ull*)(w + 4);
        ull ad0, ad1, ad2, ad3;
        DUP2(ad0, av.x); DUP2(ad1, av.y); DUP2(ad2, av.z); DUP2(ad3, av.w);
        ull ad[4] = {ad0, ad1, ad2, ad3};
        #pragma unroll
        for (int bb = 0; bb < 4; bb++) {
            FMA2(acc[bb][0], ad[bb], wrz.x);
            FMA2(acc[bb][1], ad[bb], wrz.y);
            FMA2(acc[bb][2], ad[bb], wn);
        }
    }
}

__device__ __forceinline__ void reduce3(ull acc[4][3], int kb0, int kb1, int kb2,
                                        float out[3])
{
    ull r1[2][3];
    #pragma unroll
    for (int bp = 0; bp < 2; bp++)
        #pragma unroll
        for (int g = 0; g < 3; g++) {
            ull x = acc[bp * 2][g], y = acc[bp * 2 + 1][g];
            ull give = kb0 ? x : y, keep = kb0 ? y : x;
            ull rec = __shfl_xor_sync(0xffffffffu, give, 4);
            ADD2(r1[bp][g], keep, rec);
        }
    ull r2[3];
    #pragma unroll
    for (int g = 0; g < 3; g++) {
        ull x = r1[0][g], y = r1[1][g];
        ull give = kb1 ? x : y, keep = kb1 ? y : x;
        ull rec = __shfl_xor_sync(0xffffffffu, give, 8);
        ADD2(r2[g], keep, rec);
    }
    #pragma unroll
    for (int g = 0; g < 3; g++) {
        ull rec = __shfl_xor_sync(0xffffffffu, r2[g], 16);
        ull s; ADD2(s, r2[g], rec);
        out[g] = kb2 ? hi32(s) : lo32(s);
    }
}

// ---------------- K_wc: Wc = W_ih @ W_out  + W_out transpose ----------------
__global__ void k_wc(const float* __restrict__ W_ih, const float* __restrict__ W_out)
{
    int j = blockIdx.x;
    int k = threadIdx.x;
    if (j < G3) {
        float acc = 0.f;
        #pragma unroll
        for (int x = 0; x < XX; x++)
            acc += W_ih[j * XX + x] * W_out[x * HH + k];
        g_Wc[j * HH + k] = acc;
    } else {
        int idx = (j - G3) * 256 + k;
        int h = idx >> 6, x = idx & 63;
        g_WoT[h * XX + x] = W_out[x * HH + h];
    }
}

// ---------------- K_tab: tables + composed bias ----------------
__global__ void k_init_tables(const int* __restrict__ mask0, const int* __restrict__ mask1,
                              const int* skipp,
                              const float* __restrict__ W_ih, const float* __restrict__ b_ih,
                              const float* __restrict__ b_out)
{
    int tid = threadIdx.x;
    int skip = skipp ? skipp[0] : 4;
    for (int i = tid; i < TT; i += 256) {
        g_m0f[i] = (float)mask0[i];
        g_m1f[i] = (float)mask1[i];
        int pg = (i < skip) ? 2 * i : i - skip;
        g_gidx[i] = (pg < skip) ? -1 : (pg - skip);
        int pp = (i < skip) ? 2 * i + 1 : i - skip;
        g_pidx[i] = (pp < skip) ? -1 : (pp - skip);
    }
    for (int j = tid; j < G3; j += 256) {
        float acc = b_ih[j];
        for (int x = 0; x < XX; x++) acc += W_ih[j * XX + x] * b_out[x];
        g_bc[j] = acc;
    }
}

// ---------------- K_state: init hid slot0, B slot1, counters ----------------
__global__ void k_init_state(const float* __restrict__ h_enc, const int* __restrict__ mask0)
{
    int idx = blockIdx.x * 256 + threadIdx.x;   // 0..32767
    int h = idx >> 7, b = idx & 127;
    float m0 = (float)mask0[0];
    float he = h_enc[b * HH + h];
    g_hid[h * BB + b] = m0 * he;                // hidden_0
    g_hbB[HB + h * BB + b] = he;                // B_1 = h_enc (skip_p_0 = 0)
    if (idx < 8 * 64) g_ctr[idx] = 0u;
}

// ---------------- K_main: split-pipelined recurrence + projector CTAs --------------
// sW  [256k][128f]: A-slot (whh h-pairs, 6f) at ((hg*8)^((k&7)*8)); B-slot (Wc) at +64
// sH  [256k][20f] : hidden_i tile, 16 data floats (b) + skew pad
// sB  [256k][20f] : B_{i+1} tile
// PassA (on-path): gh_i.  PassB (post-arrive slack): gi_{i+1}.
#define SW_F    (256 * 128)
#define STILE_F (256 * 20)
#define SHIST_F (16 * 256)
#define SMEM_MAIN ((SW_F + 2 * STILE_F + SHIST_F + 4 * TT) * 4)
#define NPROJ 20

__global__ void __launch_bounds__(256, 1)
k_main(const float* __restrict__ W_hh, const float* __restrict__ b_ih,
       const float* __restrict__ b_hh, const float* __restrict__ h_enc,
       float* __restrict__ out, const float* __restrict__ b_out)
{
    extern __shared__ float sm[];
    const int tid = threadIdx.x;

    if (blockIdx.x >= 128) {
        // ================= projector CTA =================
        float* sWo = sm;                   // [256h][64x]
        float* sA  = sm + 16384;           // [256h][16b]
        const int pcta = blockIdx.x - 128;
        const int b_l = tid & 15, xg = tid >> 4;

        for (int idx = tid; idx < 16384; idx += 256) sWo[idx] = g_WoT[idx];
        float bo0 = b_out[xg * 4 + 0], bo1 = b_out[xg * 4 + 1];
        float bo2 = b_out[xg * 4 + 2], bo3 = b_out[xg * 4 + 3];
        __syncthreads();

        for (int n = pcta; n < 8 * TT; n += NPROJ) {
            const int bgp = n & 7, t = n >> 3;
            if (tid == 0) {
                unsigned tgt = 8u * (unsigned)(t + 1);
                unsigned v;
                do {
                    asm volatile("ld.acquire.gpu.u32 %0, [%1];"
                                 : "=r"(v) : "l"(&g_ctr[bgp * 64]));
                } while ((int)(v - tgt) < 0);
                do {
                    asm volatile("ld.acquire.gpu.u32 %0, [%1];"
                                 : "=r"(v) : "l"(&g_ctr[bgp * 64 + 16]));
                } while ((int)(v - tgt) < 0);
            }
            __syncthreads();

            // stage B_{t+1} tile: b in [bgp*16, +16), all 256 h
            const float* src = g_hbB + (size_t)(t + 1) * HB + bgp * 16;
            #pragma unroll
            for (int it = 0; it < 4; it++) {
                int idx = it * 256 + tid;          // 0..1023
                int h = idx >> 2, q = idx & 3;
                float4 v = __ldcg((const float4*)(src + (size_t)h * BB + q * 4));
                *(float4*)(sA + h * 16 + q * 4) = v;
            }
            __syncthreads();

            ull a0 = 0ull, a1 = 0ull;
            #pragma unroll 4
            for (int h = 0; h < HH; h++) {
                float av = sA[h * 16 + b_l];
                ull ad; DUP2(ad, av);
                ulonglong2 w = *(const ulonglong2*)&sWo[h * XX + xg * 4];
                FMA2(a0, ad, w.x);
                FMA2(a1, ad, w.y);
            }
            float* dst = out + (size_t)(bgp * 16 + b_l) * TT * XX
                             + (size_t)t * XX + xg * 4;
            dst[0] = lo32(a0) + bo0;
            dst[1] = hi32(a0) + bo1;
            dst[2] = lo32(a1) + bo2;
            dst[3] = hi32(a1) + bo3;
        }
        return;
    }

    // ================= recurrence CTA =================
    float* sW    = sm;
    float* sH    = sW + SW_F;
    float* sB    = sH + STILE_F;
    float* sHist = sB + STILE_F;
    float* sM0   = sHist + SHIST_F;
    float* sM1   = sM0 + TT;
    int*   sGI   = (int*)(sM1 + TT);
    int*   sPI   = sGI + TT;

    const int bq  = tid & 3;
    const int kq  = (tid >> 2) & 7;
    const int hg  = tid >> 5;                   // warp id
    const int bg  = blockIdx.x >> 4;            // batch group
    const int hgrp= blockIdx.x & 15;
    const int b0  = bg * 16;
    const int h0  = hgrp * 16;
    const int kb0 = kq & 1, kb1 = (kq >> 1) & 1, kb2 = kq >> 2;

    const int h_m = h0 + hg * 2 + kb2;
    const int b_l = bq * 4 + (kq & 3);
    const int b_m = b0 + b_l;
    const int off = h_m * BB + b_m;

    // ---- stage weight slices (A: whh h-pairs; B: Wc h-pairs) ----
    for (int idx = tid; idx < 2048; idx += 256) {
        int k = idx >> 3, hgs = idx & 7;
        int hh0 = h0 + hgs * 2;
        float* dA = sW + (size_t)k * 128 + ((hgs * 8) ^ ((k & 7) * 8));
        float* dB = dA + 64;
        #pragma unroll
        for (int g = 0; g < 3; g++) {
            int row = g * HH + hh0;
            dA[2 * g]     = W_hh[row * HH + k];
            dA[2 * g + 1] = W_hh[(row + 1) * HH + k];
            dB[2 * g]     = g_Wc[row * HH + k];
            dB[2 * g + 1] = g_Wc[(row + 1) * HH + k];
        }
    }
    for (int idx = tid; idx < TT; idx += 256) {
        sM0[idx] = g_m0f[idx]; sM1[idx] = g_m1f[idx];
        sGI[idx] = g_gidx[idx]; sPI[idx] = g_pidx[idx];
    }

    const float bhh_n = b_hh[2 * HH + h_m];
    const float cr0 = b_hh[h_m]      + b_ih[h_m];
    const float cz0 = b_hh[HH + h_m] + b_ih[HH + h_m];
    const float cn0 = b_ih[2 * HH + h_m];
    const float crN = b_hh[h_m]      + g_bc[h_m];
    const float czN = b_hh[HH + h_m] + g_bc[HH + h_m];
    const float cnN = g_bc[2 * HH + h_m];

    float h_prev  = h_enc[b_m * HH + h_m];   // h_{i-1} carry (for reference parity only)
    float hid_own = g_m0f[0] * h_prev;
    float giP[3] = {0.f, 0.f, 0.f};          // gi_i carried (0 at i=0)
    __syncthreads();

    unsigned* ctrL = &g_ctr[bg * 64];
    unsigned* ctrH = &g_ctr[bg * 64 + 16];
    unsigned* myCtr = (hgrp < 8) ? ctrL : ctrH;

    const float* aH = sH + bq * 4;
    const float* aB = sB + bq * 4;
    const float* wA = sW + ((hg * 8) ^ (kq * 8));
    const float* wB = wA + 64;
    const int q_me = tid & 7;
    const int k_me = tid >> 3;
    const int qh   = q_me & 3;

    // precomputed cp.async smem dst (4 per chunk: sH or sB rows)
    unsigned dstc[2][4];
    #pragma unroll
    for (int it = 0; it < 4; it++) {
        int kA = it * 32 + k_me;
        float* base = (q_me < 4) ? (sH + (size_t)kA * 20 + qh * 4)
                                 : (sB + (size_t)kA * 20 + qh * 4);
        dstc[0][it] = (unsigned)__cvta_generic_to_shared(base);
        dstc[1][it] = (unsigned)__cvta_generic_to_shared(base + 128 * 20);
    }

    for (int i = 0; i < TT; i++) {
        // hoisted table reads (same-thread history)
        const int ipc = (i + 1 < TT) ? i + 1 : TT - 1;
        const int gi2 = sGI[ipc];
        float sg = (gi2 < 0) ? 0.f : sHist[(gi2 & 15) * 256 + tid];
        const int pB = sPI[ipc];
        float spB = (pB < 0) ? 0.f : sHist[(pB & 15) * 256 + tid];
        const float m0v = sM0[ipc], m1v = sM1[ipc];

        unsigned tgt = 8u * (unsigned)i;
        unsigned v;

        if (i == 4) {
            // polls (both halves)
            do { asm volatile("ld.acquire.gpu.u32 %0, [%1];" : "=r"(v) : "l"(ctrL)); }
            while ((int)(v - tgt) < 0);
            do { asm volatile("ld.acquire.gpu.u32 %0, [%1];" : "=r"(v) : "l"(ctrH)); }
            while ((int)(v - tgt) < 0);
            // on-path gi_4 from true B_4 (written at step 3)
            const float* srcB4 = g_hbB + (size_t)4 * HB;
            #pragma unroll
            for (int it = 0; it < 4; it++) {
                int idx = it * 256 + tid;
                int k = idx >> 2, q = idx & 3;
                unsigned d = (unsigned)__cvta_generic_to_shared(sB + (size_t)k * 20 + q * 4);
                CP_ASYNC16(d, (const void*)(srcB4 + (size_t)k * BB + b0 + q * 4));
            }
            CP_COMMIT(); CP_WAIT(0); __syncthreads();
            {
                ull acc4[4][3];
                #pragma unroll
                for (int bb = 0; bb < 4; bb++)
                    #pragma unroll
                    for (int g = 0; g < 3; g++) acc4[bb][g] = 0ull;
                gemm_pass(aB, wB, kq, 0, 32, acc4);
                reduce3(acc4, kb0, kb1, kb2, giP);
            }
            __syncthreads();
            // regular staging (no re-poll)
            const float* srcH = g_hid + (size_t)i * HB;
            const float* srcN = g_hbB + (size_t)(i + 1) * HB;
            #pragma unroll
            for (int c = 0; c < 2; c++) {
                #pragma unroll
                for (int it = 0; it < 4; it++) {
                    int k = c * 128 + it * 32 + k_me;
                    const float* s = (q_me < 4) ? (srcH + (size_t)k * BB + b0 + qh * 4)
                                                : (srcN + (size_t)k * BB + b0 + qh * 4);
                    CP_ASYNC16(dstc[c][it], (const void*)s);
                }
                CP_COMMIT();
            }
        } else {
            const float* srcH = g_hid + (size_t)i * HB;
            const float* srcN = g_hbB + (size_t)(i + 1) * HB;
            do { asm volatile("ld.acquire.gpu.u32 %0, [%1];" : "=r"(v) : "l"(ctrL)); }
            while ((int)(v - tgt) < 0);
            #pragma unroll
            for (int it = 0; it < 4; it++) {
                int k = it * 32 + k_me;
                const float* s = (q_me < 4) ? (srcH + (size_t)k * BB + b0 + qh * 4)
                                            : (srcN + (size_t)k * BB + b0 + qh * 4);
                CP_ASYNC16(dstc[0][it], (const void*)s);
            }
            CP_COMMIT();
            do { asm volatile("ld.acquire.gpu.u32 %0, [%1];" : "=r"(v) : "l"(ctrH)); }
            while ((int)(v - tgt) < 0);
            #pragma unroll
            for (int it = 0; it < 4; it++) {
                int k = 128 + it * 32 + k_me;
                const float* s = (q_me < 4) ? (srcH + (size_t)k * BB + b0 + qh * 4)
                                            : (srcN + (size_t)k * BB + b0 + qh * 4);
                CP_ASYNC16(dstc[1][it], (const void*)s);
            }
            CP_COMMIT();
        }

        // ---- Pass A (gh_i): chunked with cp.async overlap ----
        ull accA[4][3];
        #pragma unroll
        for (int bb = 0; bb < 4; bb++)
            #pragma unroll
            for (int g = 0; g < 3; g++) accA[bb][g] = 0ull;

        CP_WAIT(1);
        __syncthreads();
        gemm_pass(aH, wA, kq, 0, 16, accA);
        CP_WAIT(0);
        __syncthreads();
        gemm_pass(aH, wA, kq, 16, 32, accA);

        float ghA[3];
        reduce3(accA, kb0, kb1, kb2, ghA);

        // ---- GRU epilogue ----
        {
            const float cbr = i ? crN : cr0;
            const float cbz = i ? czN : cz0;
            const float cbn = i ? cnN : cn0;
            float pre_r = ghA[0] + giP[0] + cbr;
            float pre_z = ghA[1] + giP[1] + cbz;
            float ghn   = ghA[2] + bhh_n;
            float rg = __fdividef(1.f, 1.f + __expf(-pre_r));
            float zg = __fdividef(1.f, 1.f + __expf(-pre_z));
            float pre_n = giP[2] + cbn + rg * ghn;
            pre_n = fminf(fmaxf(pre_n, -15.f), 15.f);
            float e2 = __expf(2.f * pre_n);
            float ng = __fdividef(e2 - 1.f, e2 + 1.f);
            float h_new = (1.f - zg) * ng + zg * hid_own;

            if (gi2 == i) sg = h_new;            // gidx[3]==2 case (i==2)
            float hidn = m0v * h_new + m1v * sg; // hidden_{i+1}
            g_hid[(size_t)(i + 1) * HB + off] = hidn;

            if (pB == i) spB = h_new;            // pidx[2]==1 case (i==1)
            if (i != 2)
                g_hbB[(size_t)(i + 2) * HB + off] = h_new + spB;   // B_{i+2}
            if (i == 3)
                g_hbB[(size_t)4 * HB + off] = sHist[2 * 256 + tid] + h_new; // true B_4

            sHist[(i & 15) * 256 + tid] = h_new;
            hid_own = hidn;
            h_prev = h_new;
        }

        // ---- arrive, then Pass B (gi_{i+1}) in the sync slack ----
        __syncthreads();
        if (tid == 0)
            asm volatile("red.release.gpu.global.add.u32 [%0], %1;"
                         :: "l"(myCtr), "r"(1u) : "memory");

        if (i != 3) {
            ull accB[4][3];
            #pragma unroll
            for (int bb = 0; bb < 4; bb++)
                #pragma unroll
                for (int g = 0; g < 3; g++) accB[bb][g] = 0ull;
            gemm_pass(aB, wB, kq, 0, 32, accB);
            reduce3(accB, kb0, kb1, kb2, giP);
        }
        __syncthreads();                        // protect sH/sB before next staging
    }
}

// ---------------- host launch ----------------
extern "C" void kernel_launch(void* const* d_in, const int* in_sizes, int n_in,
                              void* d_out, int out_size)
{
    const float* h_enc = (const float*)d_in[1];
    const float* W_ih  = (const float*)d_in[2];
    const float* W_hh  = (const float*)d_in[3];
    const float* b_ih  = (const float*)d_in[4];
    const float* b_hh  = (const float*)d_in[5];
    const float* W_out = (const float*)d_in[6];
    const float* b_out = (const float*)d_in[7];
    const int*   mask0 = (const int*)d_in[8];
    const int*   mask1 = (const int*)d_in[9];
    const int*   skipp = (n_in > 10) ? (const int*)d_in[10] : nullptr;

    cudaFuncSetAttribute(k_main, cudaFuncAttributeMaxDynamicSharedMemorySize, SMEM_MAIN);

    k_wc<<<G3 + 64, 256>>>(W_ih, W_out);
    k_init_tables<<<1, 256>>>(mask0, mask1, skipp, W_ih, b_ih, b_out);
    k_init_state<<<128, 256>>>(h_enc, mask0);
    k_main<<<128 + NPROJ, 256, SMEM_MAIN>>>(W_hh, b_ih, b_hh, h_enc,
                                            (float*)d_out, b_out);
}